// round 1
// baseline (speedup 1.0000x reference)
#include <cuda_runtime.h>

// Problem shapes
#define N_FEAT 6
#define EMB    256
#define K1     512            // 2*EMB
#define PAIRS  15
#define M_TOT  16384          // B*S = 32*512

// Tiling
#define BM 64
#define BN 64
#define BK 16

// Static pair index order: (0,1),(0,2),...,(4,5)
__constant__ int c_i[PAIRS] = {0,0,0,0,0,1,1,1,1,2,2,2,3,3,4};
__constant__ int c_j[PAIRS] = {1,2,3,4,5,2,3,4,5,3,4,5,4,5,5};

// Scratch for h: [PAIRS][M_TOT][EMB] fp32 = 252 MB (device global: allocation-guard safe)
__device__ float g_H[(size_t)PAIRS * M_TOT * EMB];

__device__ __forceinline__ bool pair_active(const int* __restrict__ NAS, int p) {
    const int i = c_i[p], j = c_j[p];
    const int ni = (i < 2) ? 1 : NAS[i];   // nas.at[:2].set(1)
    const int nj = (j < 2) ? 1 : NAS[j];
    return (ni != 0) && (nj != 0);
}

// ---------------------------------------------------------------------------
// Kernel 1: per-pair GEMM  h[p] = tanh( [f_i | f_j] @ W_pair[p] + b_pair[p] )
// A: [M_TOT, 512] (virtual concat), B: W_pair[p] [512, 256]
// Grid: (EMB/BN, M_TOT/BM, PAIRS), 256 threads, 4x4 micro-tile.
// ---------------------------------------------------------------------------
__global__ __launch_bounds__(256, 2)
void k_pair_gemm(const float* __restrict__ feat,
                 const float* __restrict__ Wp,
                 const float* __restrict__ bp,
                 const int*   __restrict__ NAS)
{
    const int p = blockIdx.z;
    if (!pair_active(NAS, p)) return;      // zero contribution: skip entirely

    const int fi = c_i[p], fj = c_j[p];
    const int bm = blockIdx.y * BM;
    const int bn = blockIdx.x * BN;

    __shared__ float As[BK][BM];
    __shared__ float Bs[BK][BN];

    const int tid = threadIdx.x;
    const int tx  = tid & 15;          // 0..15 -> output col group (4 cols)
    const int ty  = tid >> 4;          // 0..15 -> output row group (4 rows)

    // A-tile load mapping: 64 rows x 16 k, float4 along k
    const int arow = tid >> 2;         // 0..63
    const int akq  = (tid & 3) * 4;    // 0,4,8,12
    // B-tile load mapping: 16 k x 64 cols, float4 along n
    const int brow = tid >> 4;         // 0..15
    const int bcol = (tid & 15) * 4;   // 0..60

    const float* fbase_i = feat + (size_t)fi * M_TOT * EMB;
    const float* fbase_j = feat + (size_t)fj * M_TOT * EMB;
    const float* Wbase   = Wp   + (size_t)p * K1 * EMB;

    float acc[4][4];
    #pragma unroll
    for (int a = 0; a < 4; a++)
        #pragma unroll
        for (int b = 0; b < 4; b++) acc[a][b] = 0.f;

    for (int k0 = 0; k0 < K1; k0 += BK) {
        const int kg = k0 + akq;
        const float* fb = (kg < EMB) ? fbase_i : fbase_j;
        const float4 av = *reinterpret_cast<const float4*>(
            fb + (size_t)(bm + arow) * EMB + (kg & (EMB - 1)));
        As[akq + 0][arow] = av.x;
        As[akq + 1][arow] = av.y;
        As[akq + 2][arow] = av.z;
        As[akq + 3][arow] = av.w;

        const float4 bv = *reinterpret_cast<const float4*>(
            Wbase + (size_t)(k0 + brow) * EMB + bn + bcol);
        *reinterpret_cast<float4*>(&Bs[brow][bcol]) = bv;

        __syncthreads();
        #pragma unroll
        for (int kk = 0; kk < BK; kk++) {
            const float4 a4 = *reinterpret_cast<const float4*>(&As[kk][ty * 4]);
            const float4 b4 = *reinterpret_cast<const float4*>(&Bs[kk][tx * 4]);
            const float ar[4] = {a4.x, a4.y, a4.z, a4.w};
            const float br[4] = {b4.x, b4.y, b4.z, b4.w};
            #pragma unroll
            for (int i2 = 0; i2 < 4; i2++)
                #pragma unroll
                for (int j2 = 0; j2 < 4; j2++)
                    acc[i2][j2] = fmaf(ar[i2], br[j2], acc[i2][j2]);
        }
        __syncthreads();
    }

    // Epilogue: bias + tanh, store to scratch
    const float4 bb = *reinterpret_cast<const float4*>(bp + p * EMB + bn + tx * 4);
    const float bias[4] = {bb.x, bb.y, bb.z, bb.w};
    float* Ho = g_H + ((size_t)p * M_TOT + bm) * EMB + bn;
    #pragma unroll
    for (int i2 = 0; i2 < 4; i2++) {
        float4 o;
        o.x = tanhf(acc[i2][0] + bias[0]);
        o.y = tanhf(acc[i2][1] + bias[1]);
        o.z = tanhf(acc[i2][2] + bias[2]);
        o.w = tanhf(acc[i2][3] + bias[3]);
        *reinterpret_cast<float4*>(&Ho[(size_t)(ty * 4 + i2) * EMB + tx * 4]) = o;
    }
}

// ---------------------------------------------------------------------------
// Kernel 2: out = h_flat @ W_final + b_final
// A: g_H viewed as [M_TOT, PAIRS*EMB] with col k = p*256+d -> g_H[p][m][d]
// B: W_final [3840, 256]. Skips K-chunks of inactive pairs (they are zero).
// Grid: (EMB/BN, M_TOT/BM), 256 threads, 4x4 micro-tile.
// ---------------------------------------------------------------------------
__global__ __launch_bounds__(256, 2)
void k_final_gemm(const float* __restrict__ Wf,
                  const float* __restrict__ bf,
                  const int*   __restrict__ NAS,
                  float*       __restrict__ out)
{
    const int bm = blockIdx.y * BM;
    const int bn = blockIdx.x * BN;

    __shared__ float As[BK][BM];
    __shared__ float Bs[BK][BN];

    const int tid = threadIdx.x;
    const int tx  = tid & 15;
    const int ty  = tid >> 4;

    const int arow = tid >> 2;
    const int akq  = (tid & 3) * 4;
    const int brow = tid >> 4;
    const int bcol = (tid & 15) * 4;

    float acc[4][4];
    #pragma unroll
    for (int a = 0; a < 4; a++)
        #pragma unroll
        for (int b = 0; b < 4; b++) acc[a][b] = 0.f;

    for (int p = 0; p < PAIRS; p++) {
        if (!pair_active(NAS, p)) continue;   // those K-slices are exactly zero
        const float* Hp = g_H + ((size_t)p * M_TOT + bm) * EMB;
        const float* Wb = Wf + ((size_t)p * EMB) * EMB + bn;

        for (int k0 = 0; k0 < EMB; k0 += BK) {
            const float4 av = *reinterpret_cast<const float4*>(
                Hp + (size_t)arow * EMB + k0 + akq);
            As[akq + 0][arow] = av.x;
            As[akq + 1][arow] = av.y;
            As[akq + 2][arow] = av.z;
            As[akq + 3][arow] = av.w;

            const float4 bv = *reinterpret_cast<const float4*>(
                Wb + (size_t)(k0 + brow) * EMB + bcol);
            *reinterpret_cast<float4*>(&Bs[brow][bcol]) = bv;

            __syncthreads();
            #pragma unroll
            for (int kk = 0; kk < BK; kk++) {
                const float4 a4 = *reinterpret_cast<const float4*>(&As[kk][ty * 4]);
                const float4 b4 = *reinterpret_cast<const float4*>(&Bs[kk][tx * 4]);
                const float ar[4] = {a4.x, a4.y, a4.z, a4.w};
                const float br[4] = {b4.x, b4.y, b4.z, b4.w};
                #pragma unroll
                for (int i2 = 0; i2 < 4; i2++)
                    #pragma unroll
                    for (int j2 = 0; j2 < 4; j2++)
                        acc[i2][j2] = fmaf(ar[i2], br[j2], acc[i2][j2]);
            }
            __syncthreads();
        }
    }

    // Epilogue: add b_final, store output
    const float4 bb = *reinterpret_cast<const float4*>(bf + bn + tx * 4);
    const float bias[4] = {bb.x, bb.y, bb.z, bb.w};
    #pragma unroll
    for (int i2 = 0; i2 < 4; i2++) {
        float4 o;
        o.x = acc[i2][0] + bias[0];
        o.y = acc[i2][1] + bias[1];
        o.z = acc[i2][2] + bias[2];
        o.w = acc[i2][3] + bias[3];
        *reinterpret_cast<float4*>(
            &out[(size_t)(bm + ty * 4 + i2) * EMB + bn + tx * 4]) = o;
    }
}

extern "C" void kernel_launch(void* const* d_in, const int* in_sizes, int n_in,
                              void* d_out, int out_size)
{
    const float* feat = (const float*)d_in[0];   // [6, 32, 512, 256]
    const float* Wp   = (const float*)d_in[1];   // [15, 512, 256]
    const float* bp   = (const float*)d_in[2];   // [15, 256]
    const float* Wf   = (const float*)d_in[3];   // [3840, 256]
    const float* bf   = (const float*)d_in[4];   // [256]
    const int*   NAS  = (const int*)d_in[5];     // [6]
    float* out = (float*)d_out;                  // [32, 512, 256]

    dim3 block(256);
    dim3 grid1(EMB / BN, M_TOT / BM, PAIRS);
    k_pair_gemm<<<grid1, block>>>(feat, Wp, bp, NAS);

    dim3 grid2(EMB / BN, M_TOT / BM);
    k_final_gemm<<<grid2, block>>>(Wf, bf, NAS, out);
}

// round 4
// speedup vs baseline: 1.0206x; 1.0206x over previous
#include <cuda_runtime.h>

#define EMB    256
#define K1     512
#define PAIRS  15
#define M_TOT  16384

#define BM 128
#define BN 128
#define BK 8

__constant__ int c_i[PAIRS] = {0,0,0,0,0,1,1,1,1,2,2,2,3,3,4};
__constant__ int c_j[PAIRS] = {1,2,3,4,5,2,3,4,5,3,4,5,4,5,5};

// Scratch for h: [PAIRS][M_TOT][EMB] fp32 (device global: allocation-guard safe)
__device__ float g_H[(size_t)PAIRS * M_TOT * EMB];

__device__ __forceinline__ bool pair_active(const int* __restrict__ NAS, int p) {
    const int i = c_i[p], j = c_j[p];
    const int ni = (i < 2) ? 1 : NAS[i];   // nas.at[:2].set(1)
    const int nj = (j < 2) ? 1 : NAS[j];
    return (ni != 0) && (nj != 0);
}

__device__ __forceinline__ float tanh_fast(float x) {
    float y;
    asm("tanh.approx.f32 %0, %1;" : "=f"(y) : "f"(x));
    return y;
}

// ---------------------------------------------------------------------------
// Kernel 1: h[p] = tanh( [f_i | f_j] @ W_pair[p] + b_pair[p] )
// 128x128x8 tiling, 8x8 micro-tiles, double-buffered smem.
// ---------------------------------------------------------------------------
__global__ __launch_bounds__(256, 2)
void k_pair_gemm(const float* __restrict__ feat,
                 const float* __restrict__ Wp,
                 const float* __restrict__ bp,
                 const int*   __restrict__ NAS)
{
    const int p = blockIdx.z;
    if (!pair_active(NAS, p)) return;

    const int bm = blockIdx.y * BM;
    const int bn = blockIdx.x * BN;

    __shared__ float As[2][BK][BM + 4];   // +4 pad: conflict-free transpose STS
    __shared__ float Bs[2][BK][BN];

    const int tid  = threadIdx.x;
    const int arow = tid >> 1;            // 0..127
    const int akq  = (tid & 1) * 4;       // 0 or 4
    const int bkr  = tid >> 5;            // 0..7
    const int bnc  = (tid & 31) * 4;      // 0..124
    const int tx   = tid & 15;            // output col block
    const int ty   = tid >> 4;            // output row block

    const float* fA0 = feat + (size_t)c_i[p] * M_TOT * EMB + (size_t)(bm + arow) * EMB;
    const float* fA1 = feat + (size_t)c_j[p] * M_TOT * EMB + (size_t)(bm + arow) * EMB;
    const float* Wb  = Wp + (size_t)p * K1 * EMB + bn + bnc;

    float acc[8][8];
    #pragma unroll
    for (int a = 0; a < 8; a++)
        #pragma unroll
        for (int b = 0; b < 8; b++) acc[a][b] = 0.f;

    const int NT = K1 / BK;   // 64

    // prefetch tile 0
    float4 ra, rb;
    {
        const int kg = akq;   // k0 = 0
        ra = *reinterpret_cast<const float4*>(fA0 + kg);
        rb = *reinterpret_cast<const float4*>(Wb + (size_t)bkr * EMB);
    }
    As[0][akq + 0][arow] = ra.x;
    As[0][akq + 1][arow] = ra.y;
    As[0][akq + 2][arow] = ra.z;
    As[0][akq + 3][arow] = ra.w;
    *reinterpret_cast<float4*>(&Bs[0][bkr][bnc]) = rb;
    __syncthreads();

    int buf = 0;
    for (int t = 0; t < NT; t++) {
        if (t + 1 < NT) {
            const int k0 = (t + 1) * BK;
            const int kg = k0 + akq;
            const float* src = (kg < EMB) ? (fA0 + kg) : (fA1 + kg - EMB);
            ra = *reinterpret_cast<const float4*>(src);
            rb = *reinterpret_cast<const float4*>(Wb + (size_t)(k0 + bkr) * EMB);
        }
        #pragma unroll
        for (int kk = 0; kk < BK; kk++) {
            float a[8], b[8];
            *reinterpret_cast<float4*>(&a[0]) = *reinterpret_cast<const float4*>(&As[buf][kk][ty * 8]);
            *reinterpret_cast<float4*>(&a[4]) = *reinterpret_cast<const float4*>(&As[buf][kk][ty * 8 + 4]);
            *reinterpret_cast<float4*>(&b[0]) = *reinterpret_cast<const float4*>(&Bs[buf][kk][tx * 8]);
            *reinterpret_cast<float4*>(&b[4]) = *reinterpret_cast<const float4*>(&Bs[buf][kk][tx * 8 + 4]);
            #pragma unroll
            for (int i2 = 0; i2 < 8; i2++)
                #pragma unroll
                for (int j2 = 0; j2 < 8; j2++)
                    acc[i2][j2] = fmaf(a[i2], b[j2], acc[i2][j2]);
        }
        if (t + 1 < NT) {
            const int nb = buf ^ 1;
            As[nb][akq + 0][arow] = ra.x;
            As[nb][akq + 1][arow] = ra.y;
            As[nb][akq + 2][arow] = ra.z;
            As[nb][akq + 3][arow] = ra.w;
            *reinterpret_cast<float4*>(&Bs[nb][bkr][bnc]) = rb;
        }
        __syncthreads();
        buf ^= 1;
    }

    // Epilogue: bias + tanh -> g_H
    float bias[8];
    *reinterpret_cast<float4*>(&bias[0]) =
        *reinterpret_cast<const float4*>(bp + p * EMB + bn + tx * 8);
    *reinterpret_cast<float4*>(&bias[4]) =
        *reinterpret_cast<const float4*>(bp + p * EMB + bn + tx * 8 + 4);

    float* Ho = g_H + ((size_t)p * M_TOT + bm) * EMB + bn + tx * 8;
    #pragma unroll
    for (int i2 = 0; i2 < 8; i2++) {
        const int row = ty * 8 + i2;
        float4 o0, o1;
        o0.x = tanh_fast(acc[i2][0] + bias[0]);
        o0.y = tanh_fast(acc[i2][1] + bias[1]);
        o0.z = tanh_fast(acc[i2][2] + bias[2]);
        o0.w = tanh_fast(acc[i2][3] + bias[3]);
        o1.x = tanh_fast(acc[i2][4] + bias[4]);
        o1.y = tanh_fast(acc[i2][5] + bias[5]);
        o1.z = tanh_fast(acc[i2][6] + bias[6]);
        o1.w = tanh_fast(acc[i2][7] + bias[7]);
        *reinterpret_cast<float4*>(&Ho[(size_t)row * EMB])     = o0;
        *reinterpret_cast<float4*>(&Ho[(size_t)row * EMB + 4]) = o1;
    }
}

// ---------------------------------------------------------------------------
// Kernel 2: out = h_flat @ W_final + b_final (skips inactive-pair K slices)
// Same tiling; K loop flattened over active pairs.
// ---------------------------------------------------------------------------
__global__ __launch_bounds__(256, 2)
void k_final_gemm(const float* __restrict__ Wf,
                  const float* __restrict__ bf,
                  const int*   __restrict__ NAS,
                  float*       __restrict__ out)
{
    const int bm = blockIdx.y * BM;
    const int bn = blockIdx.x * BN;

    __shared__ float As[2][BK][BM + 4];
    __shared__ float Bs[2][BK][BN];

    const int tid  = threadIdx.x;
    const int arow = tid >> 1;
    const int akq  = (tid & 1) * 4;
    const int bkr  = tid >> 5;
    const int bnc  = (tid & 31) * 4;
    const int tx   = tid & 15;
    const int ty   = tid >> 4;

    int act[PAIRS], nact = 0;
    #pragma unroll
    for (int p = 0; p < PAIRS; p++)
        if (pair_active(NAS, p)) act[nact++] = p;

    const int NT = nact * (EMB / BK);   // 32 tiles per active pair

    float acc[8][8];
    #pragma unroll
    for (int a = 0; a < 8; a++)
        #pragma unroll
        for (int b = 0; b < 8; b++) acc[a][b] = 0.f;

    float4 ra, rb;
    {
        const int p = act[0];
        ra = *reinterpret_cast<const float4*>(
            g_H + ((size_t)p * M_TOT + bm + arow) * EMB + akq);
        rb = *reinterpret_cast<const float4*>(
            Wf + ((size_t)p * EMB + bkr) * EMB + bn + bnc);
    }
    As[0][akq + 0][arow] = ra.x;
    As[0][akq + 1][arow] = ra.y;
    As[0][akq + 2][arow] = ra.z;
    As[0][akq + 3][arow] = ra.w;
    *reinterpret_cast<float4*>(&Bs[0][bkr][bnc]) = rb;
    __syncthreads();

    int buf = 0;
    for (int t = 0; t < NT; t++) {
        if (t + 1 < NT) {
            const int tn = t + 1;
            const int p  = act[tn >> 5];
            const int k0 = (tn & 31) * BK;
            ra = *reinterpret_cast<const float4*>(
                g_H + ((size_t)p * M_TOT + bm + arow) * EMB + k0 + akq);
            rb = *reinterpret_cast<const float4*>(
                Wf + ((size_t)p * EMB + k0 + bkr) * EMB + bn + bnc);
        }
        #pragma unroll
        for (int kk = 0; kk < BK; kk++) {
            float a[8], b[8];
            *reinterpret_cast<float4*>(&a[0]) = *reinterpret_cast<const float4*>(&As[buf][kk][ty * 8]);
            *reinterpret_cast<float4*>(&a[4]) = *reinterpret_cast<const float4*>(&As[buf][kk][ty * 8 + 4]);
            *reinterpret_cast<float4*>(&b[0]) = *reinterpret_cast<const float4*>(&Bs[buf][kk][tx * 8]);
            *reinterpret_cast<float4*>(&b[4]) = *reinterpret_cast<const float4*>(&Bs[buf][kk][tx * 8 + 4]);
            #pragma unroll
            for (int i2 = 0; i2 < 8; i2++)
                #pragma unroll
                for (int j2 = 0; j2 < 8; j2++)
                    acc[i2][j2] = fmaf(a[i2], b[j2], acc[i2][j2]);
        }
        if (t + 1 < NT) {
            const int nb = buf ^ 1;
            As[nb][akq + 0][arow] = ra.x;
            As[nb][akq + 1][arow] = ra.y;
            As[nb][akq + 2][arow] = ra.z;
            As[nb][akq + 3][arow] = ra.w;
            *reinterpret_cast<float4*>(&Bs[nb][bkr][bnc]) = rb;
        }
        __syncthreads();
        buf ^= 1;
    }

    float bias[8];
    *reinterpret_cast<float4*>(&bias[0]) =
        *reinterpret_cast<const float4*>(bf + bn + tx * 8);
    *reinterpret_cast<float4*>(&bias[4]) =
        *reinterpret_cast<const float4*>(bf + bn + tx * 8 + 4);

    #pragma unroll
    for (int i2 = 0; i2 < 8; i2++) {
        const int row = bm + ty * 8 + i2;
        float4 o0, o1;
        o0.x = acc[i2][0] + bias[0];
        o0.y = acc[i2][1] + bias[1];
        o0.z = acc[i2][2] + bias[2];
        o0.w = acc[i2][3] + bias[3];
        o1.x = acc[i2][4] + bias[4];
        o1.y = acc[i2][5] + bias[5];
        o1.z = acc[i2][6] + bias[6];
        o1.w = acc[i2][7] + bias[7];
        *reinterpret_cast<float4*>(&out[(size_t)row * EMB + bn + tx * 8])     = o0;
        *reinterpret_cast<float4*>(&out[(size_t)row * EMB + bn + tx * 8 + 4]) = o1;
    }
}

extern "C" void kernel_launch(void* const* d_in, const int* in_sizes, int n_in,
                              void* d_out, int out_size)
{
    const float* feat = (const float*)d_in[0];   // [6, 32, 512, 256]
    const float* Wp   = (const float*)d_in[1];   // [15, 512, 256]
    const float* bp   = (const float*)d_in[2];   // [15, 256]
    const float* Wf   = (const float*)d_in[3];   // [3840, 256]
    const float* bf   = (const float*)d_in[4];   // [256]
    const int*   NAS  = (const int*)d_in[5];     // [6]
    float* out = (float*)d_out;                  // [32, 512, 256]

    dim3 block(256);
    dim3 grid1(EMB / BN, M_TOT / BM, PAIRS);
    k_pair_gemm<<<grid1, block>>>(feat, Wp, bp, NAS);

    dim3 grid2(EMB / BN, M_TOT / BM);
    k_final_gemm<<<grid2, block>>>(Wf, bf, NAS, out);
}

// round 12
// speedup vs baseline: 2.4421x; 2.3928x over previous
#include <cuda_runtime.h>
#include <cuda_bf16.h>
#include <cstdint>

#define EMB    256
#define K1     512
#define PAIRS  15
#define M_TOT  16384
#define KF     3840            // PAIRS*EMB

__constant__ int c_i[PAIRS] = {0,0,0,0,0,1,1,1,1,2,2,2,3,3,4};
__constant__ int c_j[PAIRS] = {1,2,3,4,5,2,3,4,5,3,4,5,4,5,5};

// Scratch (device globals: allocation-guard safe)
__device__ __nv_bfloat16 g_Wphi[(size_t)PAIRS * EMB * K1];   // W_pair^T hi  [p][n][k]
__device__ __nv_bfloat16 g_Wplo[(size_t)PAIRS * EMB * K1];   // W_pair^T lo
__device__ __nv_bfloat16 g_Wfhi[(size_t)EMB * KF];           // W_final^T hi [n][k]
__device__ __nv_bfloat16 g_Wflo[(size_t)EMB * KF];           // W_final^T lo
__device__ __nv_bfloat16 g_Hhi[(size_t)PAIRS * M_TOT * EMB]; // h hi [p][m][d]
__device__ __nv_bfloat16 g_Hlo[(size_t)PAIRS * M_TOT * EMB]; // h lo

__device__ __forceinline__ bool pair_active(const int* __restrict__ NAS, int p) {
    const int i = c_i[p], j = c_j[p];
    const int ni = (i < 2) ? 1 : NAS[i];
    const int nj = (j < 2) ? 1 : NAS[j];
    return (ni != 0) && (nj != 0);
}

__device__ __forceinline__ float tanh_fast(float x) {
    float y; asm("tanh.approx.f32 %0, %1;" : "=f"(y) : "f"(x)); return y;
}
__device__ __forceinline__ uint32_t s2u(const void* p) {
    uint32_t a;
    asm("{ .reg .u64 t; cvta.to.shared.u64 t, %1; cvt.u32.u64 %0, t; }" : "=r"(a) : "l"(p));
    return a;
}
// pack (x,y) -> bf16x2 with x in low half (memory order [x,y])
__device__ __forceinline__ uint32_t packbf(float x, float y) {
    uint32_t r; asm("cvt.rn.bf16x2.f32 %0, %1, %2;" : "=r"(r) : "f"(y), "f"(x));
    return r;
}
// residual pair: lo = val - float(hi)
__device__ __forceinline__ uint32_t lopair(uint32_t hp, float x, float y) {
    float hx = __uint_as_float(hp << 16);
    float hy = __uint_as_float(hp & 0xffff0000u);
    return packbf(x - hx, y - hy);
}
__device__ __forceinline__ void ldsm4(uint32_t* r, uint32_t addr) {
    asm volatile("ldmatrix.sync.aligned.m8n8.x4.shared.b16 {%0,%1,%2,%3}, [%4];"
                 : "=r"(r[0]), "=r"(r[1]), "=r"(r[2]), "=r"(r[3]) : "r"(addr));
}
__device__ __forceinline__ void mma16816(float* d, const uint32_t* a, uint32_t b0, uint32_t b1) {
    asm volatile("mma.sync.aligned.m16n8k16.row.col.f32.bf16.bf16.f32 "
                 "{%0,%1,%2,%3}, {%4,%5,%6,%7}, {%8,%9}, {%0,%1,%2,%3};"
                 : "+f"(d[0]), "+f"(d[1]), "+f"(d[2]), "+f"(d[3])
                 : "r"(a[0]), "r"(a[1]), "r"(a[2]), "r"(a[3]), "r"(b0), "r"(b1));
}
__device__ __forceinline__ void cpa16(uint32_t dst, const void* src) {
    asm volatile("cp.async.cg.shared.global [%0], [%1], 16;" :: "r"(dst), "l"(src));
}
#define CP_COMMIT() asm volatile("cp.async.commit_group;" ::: "memory")
#define CP_WAIT0()  asm volatile("cp.async.wait_group 0;" ::: "memory")

// SMEM layout: bias[128]f at 0, stages at 1024. Stage: AHI|ALO|BHI|BLO 16KB each.
#define ST_A_HI 0
#define ST_A_LO 16384
#define ST_B_HI 32768
#define ST_B_LO 49152
#define STAGE   65536
#define SM_STG  1024
#define SMEM_BYTES (SM_STG + 2 * STAGE)   // 132096

// smem tile byte offset for (row, 16B-chunk u): 128B rows, XOR swizzle
__device__ __forceinline__ uint32_t swoff(int row, int u) {
    return (uint32_t)(row * 128 + ((u ^ (row & 7)) << 4));
}

// ---------------- shared compute: one BK=64 stage of split-bf16 MMA ----------
__device__ __forceinline__ void stage_mma(uint32_t stb, int warp_m, int warp_n,
                                          int lane, float acc[2][8][4]) {
    const int l15 = lane & 15, lh = lane >> 4;
    uint32_t aoff[2], boff[4];
    int asw[2], bsw[4];
    #pragma unroll
    for (int mi = 0; mi < 2; mi++) {
        int r = warp_m * 32 + mi * 16 + l15;
        aoff[mi] = r * 128; asw[mi] = r & 7;
    }
    #pragma unroll
    for (int ng = 0; ng < 4; ng++) {
        int r = warp_n * 64 + ng * 16 + l15;
        boff[ng] = r * 128; bsw[ng] = r & 7;
    }
    #pragma unroll
    for (int kk = 0; kk < 4; kk++) {
        const int ch = kk * 2 + lh;
        uint32_t ah[2][4], al[2][4];
        #pragma unroll
        for (int mi = 0; mi < 2; mi++) {
            ldsm4(ah[mi], stb + ST_A_HI + aoff[mi] + (((ch ^ asw[mi]) & 7) << 4));
            ldsm4(al[mi], stb + ST_A_LO + aoff[mi] + (((ch ^ asw[mi]) & 7) << 4));
        }
        #pragma unroll
        for (int ng = 0; ng < 4; ng++) {
            uint32_t bh[4], bl[4];
            ldsm4(bh, stb + ST_B_HI + boff[ng] + (((ch ^ bsw[ng]) & 7) << 4));
            ldsm4(bl, stb + ST_B_LO + boff[ng] + (((ch ^ bsw[ng]) & 7) << 4));
            #pragma unroll
            for (int mi = 0; mi < 2; mi++) {
                mma16816(acc[mi][ng * 2 + 0], ah[mi], bh[0], bh[2]);
                mma16816(acc[mi][ng * 2 + 0], ah[mi], bl[0], bl[2]);
                mma16816(acc[mi][ng * 2 + 0], al[mi], bh[0], bh[2]);
                mma16816(acc[mi][ng * 2 + 1], ah[mi], bh[1], bh[3]);
                mma16816(acc[mi][ng * 2 + 1], ah[mi], bl[1], bl[3]);
                mma16816(acc[mi][ng * 2 + 1], al[mi], bh[1], bh[3]);
            }
        }
    }
}

// ---------------------------------------------------------------------------
// Prep: transpose + bf16-split weights
// ---------------------------------------------------------------------------
__global__ void prep_wp(const float* __restrict__ Wp, const int* __restrict__ NAS) {
    const int p = blockIdx.z;
    if (!pair_active(NAS, p)) return;
    __shared__ float t[64][65];
    const int k0 = blockIdx.x * 64, n0 = blockIdx.y * 64;
    const int tid = threadIdx.x;
    #pragma unroll
    for (int i = 0; i < 16; i++) {
        int idx = i * 256 + tid; int r = idx >> 6, c = idx & 63;
        t[r][c] = Wp[((size_t)p * K1 + k0 + r) * EMB + n0 + c];
    }
    __syncthreads();
    #pragma unroll
    for (int i = 0; i < 16; i++) {
        int idx = i * 256 + tid; int r = idx >> 6, c = idx & 63;
        float x = t[c][r];
        __nv_bfloat16 h = __float2bfloat16(x);
        size_t o = ((size_t)p * EMB + n0 + r) * K1 + k0 + c;
        g_Wphi[o] = h;
        g_Wplo[o] = __float2bfloat16(x - __bfloat162float(h));
    }
}
__global__ void prep_wf(const float* __restrict__ Wf, const int* __restrict__ NAS) {
    const int k0 = blockIdx.x * 64;
    if (!pair_active(NAS, k0 >> 8)) return;
    __shared__ float t[64][65];
    const int n0 = blockIdx.y * 64;
    const int tid = threadIdx.x;
    #pragma unroll
    for (int i = 0; i < 16; i++) {
        int idx = i * 256 + tid; int r = idx >> 6, c = idx & 63;
        t[r][c] = Wf[(size_t)(k0 + r) * EMB + n0 + c];
    }
    __syncthreads();
    #pragma unroll
    for (int i = 0; i < 16; i++) {
        int idx = i * 256 + tid; int r = idx >> 6, c = idx & 63;
        float x = t[c][r];
        __nv_bfloat16 h = __float2bfloat16(x);
        size_t o = (size_t)(n0 + r) * KF + k0 + c;
        g_Wfhi[o] = h;
        g_Wflo[o] = __float2bfloat16(x - __bfloat162float(h));
    }
}

// ---------------------------------------------------------------------------
// GEMM1: h[p] = tanh([f_i|f_j] @ W_p + b_p)   (HMMA, split-bf16 3-pass)
// grid: (128 Mtiles * 2 Ntiles, PAIRS)
// ---------------------------------------------------------------------------
__global__ __launch_bounds__(256, 1)
void k_pair_mma(const float* __restrict__ feat, const float* __restrict__ bp,
                const int* __restrict__ NAS)
{
    extern __shared__ char smem[];
    const int p = blockIdx.y;
    if (!pair_active(NAS, p)) return;
    const int tid = threadIdx.x, lane = tid & 31, wid = tid >> 5;
    const int warp_m = wid & 3, warp_n = wid >> 2;
    const int bm = (blockIdx.x >> 1) * 128, bn = (blockIdx.x & 1) * 128;
    const uint32_t sb = s2u(smem);
    float* bias_s = (float*)smem;
    if (tid < 32) ((float4*)bias_s)[tid] = ((const float4*)(bp + p * EMB + bn))[tid];

    const __nv_bfloat16* WH = g_Wphi + ((size_t)p * EMB + bn) * K1;
    const __nv_bfloat16* WL = g_Wplo + ((size_t)p * EMB + bn) * K1;

    float acc[2][8][4];
    #pragma unroll
    for (int a = 0; a < 2; a++)
        #pragma unroll
        for (int b = 0; b < 8; b++)
            #pragma unroll
            for (int c = 0; c < 4; c++) acc[a][b][c] = 0.f;

    const int NT = K1 / 64;   // 8
    float4 av[4][2];

    auto issueB = [&](int t, int buf) {
        const int k0 = t * 64;
        #pragma unroll
        for (int it = 0; it < 4; it++) {
            int c = it * 256 + tid; int row = c >> 3, u = c & 7;
            uint32_t d = sb + SM_STG + buf * STAGE + swoff(row, u);
            cpa16(d + ST_B_HI, WH + (size_t)row * K1 + k0 + u * 8);
            cpa16(d + ST_B_LO, WL + (size_t)row * K1 + k0 + u * 8);
        }
    };
    auto ldgA = [&](int t) {
        const int k0 = t * 64;
        const int f  = (k0 < EMB) ? c_i[p] : c_j[p];
        const float* A = feat + ((size_t)f * M_TOT + bm) * EMB + (k0 & (EMB - 1));
        #pragma unroll
        for (int it = 0; it < 4; it++) {
            int c = it * 256 + tid; int row = c >> 3, u = c & 7;
            av[it][0] = *reinterpret_cast<const float4*>(A + (size_t)row * EMB + u * 8);
            av[it][1] = *reinterpret_cast<const float4*>(A + (size_t)row * EMB + u * 8 + 4);
        }
    };
    auto stsA = [&](int buf) {
        #pragma unroll
        for (int it = 0; it < 4; it++) {
            int c = it * 256 + tid; int row = c >> 3, u = c & 7;
            uint4 hq, lq;
            hq.x = packbf(av[it][0].x, av[it][0].y); lq.x = lopair(hq.x, av[it][0].x, av[it][0].y);
            hq.y = packbf(av[it][0].z, av[it][0].w); lq.y = lopair(hq.y, av[it][0].z, av[it][0].w);
            hq.z = packbf(av[it][1].x, av[it][1].y); lq.z = lopair(hq.z, av[it][1].x, av[it][1].y);
            hq.w = packbf(av[it][1].z, av[it][1].w); lq.w = lopair(hq.w, av[it][1].z, av[it][1].w);
            char* base = smem + SM_STG + buf * STAGE + swoff(row, u);
            *reinterpret_cast<uint4*>(base + ST_A_HI) = hq;
            *reinterpret_cast<uint4*>(base + ST_A_LO) = lq;
        }
    };

    // prologue
    issueB(0, 0); CP_COMMIT();
    ldgA(0); stsA(0);
    CP_WAIT0(); __syncthreads();

    for (int t = 0; t < NT; t++) {
        const int buf = t & 1;
        if (t + 1 < NT) { issueB(t + 1, buf ^ 1); CP_COMMIT(); ldgA(t + 1); }
        stage_mma(sb + SM_STG + buf * STAGE, warp_m, warp_n, lane, acc);
        if (t + 1 < NT) stsA(buf ^ 1);
        CP_WAIT0(); __syncthreads();
    }

    // epilogue: bias + tanh -> hi/lo bf16 in g_H
    const int r0 = lane >> 2, c2 = (lane & 3) * 2;
    #pragma unroll
    for (int mi = 0; mi < 2; mi++)
        #pragma unroll
        for (int hf = 0; hf < 2; hf++) {
            const int m = bm + warp_m * 32 + mi * 16 + r0 + hf * 8;
            const size_t rb = ((size_t)p * M_TOT + m) * EMB + bn + warp_n * 64;
            #pragma unroll
            for (int ni = 0; ni < 8; ni++) {
                const int col = ni * 8 + c2;
                float x0 = tanh_fast(acc[mi][ni][hf * 2 + 0] + bias_s[warp_n * 64 + col]);
                float x1 = tanh_fast(acc[mi][ni][hf * 2 + 1] + bias_s[warp_n * 64 + col + 1]);
                uint32_t hp = packbf(x0, x1);
                uint32_t lp = lopair(hp, x0, x1);
                *reinterpret_cast<uint32_t*>(g_Hhi + rb + col) = hp;
                *reinterpret_cast<uint32_t*>(g_Hlo + rb + col) = lp;
            }
        }
}

// ---------------------------------------------------------------------------
// GEMM2: out = h_flat @ W_final + b_final (active pairs only)
// grid: 128 Mtiles * 2 Ntiles
// ---------------------------------------------------------------------------
__global__ __launch_bounds__(256, 1)
void k_final_mma(const float* __restrict__ bf, const int* __restrict__ NAS,
                 float* __restrict__ out)
{
    extern __shared__ char smem[];
    const int tid = threadIdx.x, lane = tid & 31, wid = tid >> 5;
    const int warp_m = wid & 3, warp_n = wid >> 2;
    const int bm = (blockIdx.x >> 1) * 128, bn = (blockIdx.x & 1) * 128;
    const uint32_t sb = s2u(smem);
    float* bias_s = (float*)smem;
    if (tid < 32) ((float4*)bias_s)[tid] = ((const float4*)(bf + bn))[tid];

    int act[PAIRS]; int nact = 0;
    #pragma unroll
    for (int p = 0; p < PAIRS; p++)
        if (pair_active(NAS, p)) act[nact++] = p;
    const int NT = nact * 4;

    float acc[2][8][4];
    #pragma unroll
    for (int a = 0; a < 2; a++)
        #pragma unroll
        for (int b = 0; b < 8; b++)
            #pragma unroll
            for (int c = 0; c < 4; c++) acc[a][b][c] = 0.f;

    auto issue = [&](int t, int buf) {
        const int p  = act[t >> 2];
        const int k0 = (t & 3) * 64;
        const __nv_bfloat16* HH = g_Hhi + ((size_t)p * M_TOT + bm) * EMB + k0;
        const __nv_bfloat16* HL = g_Hlo + ((size_t)p * M_TOT + bm) * EMB + k0;
        const __nv_bfloat16* WH = g_Wfhi + (size_t)bn * KF + p * EMB + k0;
        const __nv_bfloat16* WL = g_Wflo + (size_t)bn * KF + p * EMB + k0;
        #pragma unroll
        for (int it = 0; it < 4; it++) {
            int c = it * 256 + tid; int row = c >> 3, u = c & 7;
            uint32_t d = sb + SM_STG + buf * STAGE + swoff(row, u);
            cpa16(d + ST_A_HI, HH + (size_t)row * EMB + u * 8);
            cpa16(d + ST_A_LO, HL + (size_t)row * EMB + u * 8);
            cpa16(d + ST_B_HI, WH + (size_t)row * KF + u * 8);
            cpa16(d + ST_B_LO, WL + (size_t)row * KF + u * 8);
        }
    };

    issue(0, 0); CP_COMMIT();
    CP_WAIT0(); __syncthreads();

    for (int t = 0; t < NT; t++) {
        const int buf = t & 1;
        if (t + 1 < NT) { issue(t + 1, buf ^ 1); CP_COMMIT(); }
        stage_mma(sb + SM_STG + buf * STAGE, warp_m, warp_n, lane, acc);
        CP_WAIT0(); __syncthreads();
    }

    const int r0 = lane >> 2, c2 = (lane & 3) * 2;
    #pragma unroll
    for (int mi = 0; mi < 2; mi++)
        #pragma unroll
        for (int hf = 0; hf < 2; hf++) {
            const int m = bm + warp_m * 32 + mi * 16 + r0 + hf * 8;
            float* ob = out + (size_t)m * EMB + bn + warp_n * 64;
            #pragma unroll
            for (int ni = 0; ni < 8; ni++) {
                const int col = ni * 8 + c2;
                float2 v;
                v.x = acc[mi][ni][hf * 2 + 0] + bias_s[warp_n * 64 + col];
                v.y = acc[mi][ni][hf * 2 + 1] + bias_s[warp_n * 64 + col + 1];
                *reinterpret_cast<float2*>(ob + col) = v;
            }
        }
}

extern "C" void kernel_launch(void* const* d_in, const int* in_sizes, int n_in,
                              void* d_out, int out_size)
{
    const float* feat = (const float*)d_in[0];   // [6, 32, 512, 256]
    const float* Wp   = (const float*)d_in[1];   // [15, 512, 256]
    const float* bp   = (const float*)d_in[2];   // [15, 256]
    const float* Wf   = (const float*)d_in[3];   // [3840, 256]
    const float* bf   = (const float*)d_in[4];   // [256]
    const int*   NAS  = (const int*)d_in[5];     // [6]
    float* out = (float*)d_out;                  // [32, 512, 256]

    cudaFuncSetAttribute(k_pair_mma,  cudaFuncAttributeMaxDynamicSharedMemorySize, SMEM_BYTES);
    cudaFuncSetAttribute(k_final_mma, cudaFuncAttributeMaxDynamicSharedMemorySize, SMEM_BYTES);

    prep_wp<<<dim3(K1 / 64, EMB / 64, PAIRS), 256>>>(Wp, NAS);
    prep_wf<<<dim3(KF / 64, EMB / 64), 256>>>(Wf, NAS);

    k_pair_mma<<<dim3(256, PAIRS), 256, SMEM_BYTES>>>(feat, bp, NAS);
    k_final_mma<<<256, 256, SMEM_BYTES>>>(bf, NAS, out);
}